// round 9
// baseline (speedup 1.0000x reference)
#include <cuda_runtime.h>
#include <math.h>

#define NN 63
#define NP (NN*NN)          // 3969
#define BATCH 256
#define KS 7
#define ML 3

// ---------------- device scratch ----------------
__device__ float g_csT[63*68*2];  // interleaved (cos,sin) [k][n], cols 63..67 zero
__device__ float g_cosTT[63*36];  // transposed [n][k2<32], stride 36
__device__ float g_sinTT[63*36];
__device__ float g_w1[BATCH*147];
__device__ float g_w2[BATCH*147];
__device__ float g_a4[BATCH*1089*32];   // [b][pix][ch]
__device__ float g_blocksum[BATCH];

__device__ __forceinline__ float gelu_exact(float v) {
    return v * 0.5f * (1.0f + erff(v * 0.70710678118654752f));
}

__global__ void init_tw_kernel() {
    int idx = blockIdx.x * blockDim.x + threadIdx.x;
    if (idx < 63*68) {
        int k = idx / 68, n = idx % 68;
        float c = 0.f, s = 0.f;
        if (n < 63) {
            float ang = 6.28318530717958647692f * (float)((k * n) % NN) / 63.0f;
            c = cosf(ang); s = sinf(ang);
        }
        g_csT[idx*2] = c;
        g_csT[idx*2 + 1] = s;
    }
    if (idx < 63*36) {
        int n = idx / 36, k2 = idx % 36;
        if (k2 < 32) {
            float ang = 6.28318530717958647692f * (float)((k2 * n) % NN) / 63.0f;
            g_cosTT[idx] = cosf(ang);
            g_sinTT[idx] = sinf(ang);
        } else { g_cosTT[idx] = 0.f; g_sinTT[idx] = 0.f; }
    }
}

// ---------------- hypernet ----------------
__global__ void hyper_kernel(const float* __restrict__ kA,
                             const float* __restrict__ w1a, const float* __restrict__ b1a,
                             const float* __restrict__ w2a, const float* __restrict__ b2a,
                             const float* __restrict__ w1b, const float* __restrict__ b1b,
                             const float* __restrict__ w2b, const float* __restrict__ b2b) {
    int b = blockIdx.x;
    __shared__ float a[9], h1[100], h2[100];
    int t = threadIdx.x;
    if (t < 9) a[t] = kA[b*9 + t];
    __syncthreads();
    if (t < 100) {
        float s = b1a[t];
        #pragma unroll
        for (int i = 0; i < 9; i++) s += a[i] * w1a[i*100 + t];
        h1[t] = gelu_exact(s);
    } else if (t < 200) {
        int h = t - 100;
        float s = b1b[h];
        #pragma unroll
        for (int i = 0; i < 9; i++) s += a[i] * w1b[i*100 + h];
        h2[h] = gelu_exact(s);
    }
    __syncthreads();
    for (int o = t; o < 147; o += blockDim.x) {
        float s1 = b2a[o], s2 = b2b[o];
        for (int h = 0; h < 100; h++) {
            s1 += h1[h] * w2a[h*147 + o];
            s2 += h2[h] * w2b[h*147 + o];
        }
        g_w1[b*147 + o] = s1;
        g_w2[b*147 + o] = s2;
    }
}

// ---------------- fused ConvTranspose chain ct1..ct4 ----------------
__device__ __forceinline__ void load_ctw(const float* __restrict__ w,
                                         const float* __restrict__ bias,
                                         float* s_w, float* s_bias, int tid) {
    for (int idx = tid; idx < 9216; idx += 512) {
        int i = idx & 31, o = (idx >> 5) & 31, k = idx >> 10;
        s_w[k*1040 + (o>>3)*260 + (o&7)*32 + i] = w[(i*32 + o)*9 + k];
    }
    if (tid < 32) s_bias[tid] = bias[tid];
}

template<int IN_H>
__device__ void ct_midstage(const float* __restrict__ s_in, const float* __restrict__ s_w,
                            const float* __restrict__ s_bias, float* __restrict__ out, int tid) {
    constexpr int OUT_H = 2*IN_H - 1;
    constexpr int OUT_SZ = OUT_H*OUT_H;
    const float4* in4 = (const float4*)s_in;
    const float4* w4  = (const float4*)s_w;
    for (int it = tid; it < OUT_SZ*4; it += 512) {
        int pix = it >> 2, og = it & 3;
        int y = pix / OUT_H, x = pix % OUT_H;
        float acc[8];
        #pragma unroll
        for (int ol = 0; ol < 8; ol++) acc[ol] = s_bias[og*8 + ol];
        int kys[2], iys[2], nky, kxs[2], ixs[2], nkx;
        if (y & 1) { nky=2; kys[0]=0; iys[0]=(y+1)>>1; kys[1]=2; iys[1]=(y-1)>>1; }
        else       { nky=1; kys[0]=1; iys[0]=y>>1; }
        if (x & 1) { nkx=2; kxs[0]=0; ixs[0]=(x+1)>>1; kxs[1]=2; ixs[1]=(x-1)>>1; }
        else       { nkx=1; kxs[0]=1; ixs[0]=x>>1; }
        for (int p = 0; p < nky; p++)
            for (int q = 0; q < nkx; q++) {
                int base4 = (iys[p]*IN_H + ixs[q]) * 8;
                const float4* wrow = w4 + (kys[p]*3 + kxs[q])*260 + og*65;
                #pragma unroll
                for (int c4 = 0; c4 < 8; c4++) {
                    float4 v = in4[base4 + c4];
                    #pragma unroll
                    for (int ol = 0; ol < 8; ol++) {
                        float4 wv = wrow[ol*8 + c4];
                        acc[ol] += v.x*wv.x + v.y*wv.y + v.z*wv.z + v.w*wv.w;
                    }
                }
            }
        float* ob = out + pix*32 + og*8;
        float4 o0 = {gelu_exact(acc[0]), gelu_exact(acc[1]), gelu_exact(acc[2]), gelu_exact(acc[3])};
        float4 o1 = {gelu_exact(acc[4]), gelu_exact(acc[5]), gelu_exact(acc[6]), gelu_exact(acc[7])};
        *(float4*)ob = o0;
        *(float4*)(ob + 4) = o1;
    }
}

__global__ void __launch_bounds__(512) ctchain_kernel(
    const float* __restrict__ kA,
    const float* __restrict__ w1c, const float* __restrict__ b1c,
    const float* __restrict__ w2c, const float* __restrict__ b2c,
    const float* __restrict__ w3c, const float* __restrict__ b3c,
    const float* __restrict__ w4c, const float* __restrict__ b4c) {
    extern __shared__ float cs[];
    float* s_w    = cs;               // 9360
    float* B1     = cs + 9360;        // 9248
    float* B2     = B1 + 9248;        // 2592
    float* s_a    = B2 + 2592;        // 16
    float* s_bias = s_a + 16;         // 32
    int b = blockIdx.x, tid = threadIdx.x;

    if (tid < 9) s_a[tid] = kA[b*9 + tid];
    load_ctw(w2c, b2c, s_w, s_bias, tid);
    __syncthreads();

    for (int el = tid; el < 800; el += 512) {
        int pix = el >> 5, o = el & 31;
        int y = pix / 5, x = pix % 5;
        float acc = b1c[o];
        int kys[2], iys[2], nky, kxs[2], ixs[2], nkx;
        if (y & 1) { nky=2; kys[0]=0; iys[0]=(y+1)>>1; kys[1]=2; iys[1]=(y-1)>>1; }
        else       { nky=1; kys[0]=1; iys[0]=y>>1; }
        if (x & 1) { nkx=2; kxs[0]=0; ixs[0]=(x+1)>>1; kxs[1]=2; ixs[1]=(x-1)>>1; }
        else       { nkx=1; kxs[0]=1; ixs[0]=x>>1; }
        for (int p = 0; p < nky; p++)
            for (int q = 0; q < nkx; q++)
                acc += s_a[iys[p]*3 + ixs[q]] * w1c[o*9 + kys[p]*3 + kxs[q]];
        B1[pix*32 + o] = gelu_exact(acc);
    }
    __syncthreads();

    ct_midstage<5>(B1, s_w, s_bias, B2, tid);
    __syncthreads();
    load_ctw(w3c, b3c, s_w, s_bias, tid);
    __syncthreads();
    ct_midstage<9>(B2, s_w, s_bias, B1, tid);
    __syncthreads();
    load_ctw(w4c, b4c, s_w, s_bias, tid);
    __syncthreads();
    ct_midstage<17>(B1, s_w, s_bias, g_a4 + (size_t)b*1089*32, tid);
}

// ---------------- persistent per-sample solver ----------------
#define O_SXP 0                      // 65x68 = 4420
#define O_SRP 4420                   // 69x72 = 4968
#define O_T   9388                   // 3*4968 = 14904 (ct5 staging 7938 fits)
#define O_PR  24292                  // [m][36] = 2268
#define O_PI  26560
#define O_CR  28828                  // [k1][36] = 2268
#define O_CI  31096
#define O_DR  33364                  // [m][36] = 2268
#define O_DI  35632
#define O_WCR 37900                  // [k1][36] = 2268
#define O_WCI 40168
#define O_CS  42436                  // interleaved (c,s) [k][68] = 8568
#define O_TTC 51004                  // [n][36] = 2268
#define O_TTS 53272
#define O_W5  55540                  // 576
#define O_W1  56116                  // 160
#define O_W2  56276
#define O_KA  56436
#define SMEM_FLOATS 56452            // 225808 B

__global__ void __launch_bounds__(512) solver_kernel(const float* __restrict__ x_in,
                              const float* __restrict__ f_in,
                              const float* __restrict__ kA,
                              const float* __restrict__ w5, const float* __restrict__ b5) {
    extern __shared__ float sm[];
    float* sxp  = sm + O_SXP;
    float* srp  = sm + O_SRP;
    float* sT   = sm + O_T;
    float* sPr  = sm + O_PR;
    float* sPi  = sm + O_PI;
    float* sCr  = sm + O_CR;
    float* sCi  = sm + O_CI;
    float* sDr  = sm + O_DR;
    float* sDi  = sm + O_DI;
    float* swcr = sm + O_WCR;
    float* swci = sm + O_WCI;
    float* scs  = sm + O_CS;
    float* sttc = sm + O_TTC;
    float* stts = sm + O_TTS;
    float* sw5  = sm + O_W5;
    float* sw1  = sm + O_W1;
    float* sw2  = sm + O_W2;
    float* ska  = sm + O_KA;

    int b = blockIdx.x, tid = threadIdx.x;
    const int T = 512;
    const float inv = 0.12598815766974242f;  // 1/sqrt(63)

    // ---- init ----
    // f registers: work item w = tid + p*512 (w < 1008): i = w>>4, j0 = (w&15)*4
    float4 fr4[2];
    #pragma unroll
    for (int p = 0; p < 2; p++) {
        int w = tid + p*T;
        fr4[p] = make_float4(0.f, 0.f, 0.f, 0.f);
        if (w < 1008) {
            int i = w >> 4, j0 = (w & 15) << 2;
            const float* fb = f_in + b*NP + i*NN;
            float v[4];
            #pragma unroll
            for (int l = 0; l < 4; l++) v[l] = (j0 + l < 63) ? fb[j0 + l] : 0.f;
            fr4[p] = make_float4(v[0], v[1], v[2], v[3]);
        }
    }
    for (int el = tid; el < NP; el += T) {
        int i = el / NN, j = el % NN;
        sxp[(i+1)*68 + (j+1)] = x_in[b*NP + el];
    }
    for (int el = tid; el < 63*68*2; el += T) scs[el] = g_csT[el];
    for (int el = tid; el < 63*36; el += T) { sttc[el] = g_cosTT[el]; stts[el] = g_sinTT[el]; }
    for (int c = tid; c < 65; c += T) {
        sxp[c] = (c == 64) ? 1.f : 0.f;
        sxp[64*68 + c] = 1.f;
    }
    for (int r = tid; r < 65; r += T) {
        sxp[r*68] = (r == 64) ? 1.f : 0.f;
        sxp[r*68 + 64] = 1.f;
        sxp[r*68 + 65] = 0.f;
        sxp[r*68 + 66] = 0.f;
        sxp[r*68 + 67] = 0.f;
    }
    for (int idx = tid; idx < 576; idx += T) {
        int k = idx / 64, r = idx & 63, o = r >> 5, i = r & 31;
        sw5[idx] = w5[i*18 + o*9 + k];
    }
    if (tid < 9) ska[tid] = kA[b*9 + tid];
    for (int el = tid; el < 147; el += T) {
        sw1[el] = g_w1[b*147 + el];
        sw2[el] = g_w2[b*147 + el];
    }
    __syncthreads();

    // registerize stencil
    float k0 = ska[0], k1 = ska[1], k2v = ska[2],
          k3 = ska[3], k4 = ska[4], k5 = ska[5],
          k6 = ska[6], k7 = ska[7], k8 = ska[8];

    // ---- ct5 fused: h flat [2][63*63] into sT staging ----
    {
        float b0 = b5[0], b1 = b5[1];
        const float4* s_w4 = (const float4*)sw5;
        const float4* gin = (const float4*)(g_a4 + (size_t)b * 1089 * 32);
        for (int pix = tid; pix < NP; pix += T) {
            int y = pix / NN, x = pix % NN;
            float acc0 = b0, acc1 = b1;
            int kys[2], iys[2], nky, kxs[2], ixs[2], nkx;
            if (y & 1) { nky=1; kys[0]=1; iys[0]=(y+1)>>1; }
            else       { nky=2; kys[0]=0; iys[0]=(y+2)>>1; kys[1]=2; iys[1]=y>>1; }
            if (x & 1) { nkx=1; kxs[0]=1; ixs[0]=(x+1)>>1; }
            else       { nkx=2; kxs[0]=0; ixs[0]=(x+2)>>1; kxs[1]=2; ixs[1]=x>>1; }
            for (int p = 0; p < nky; p++)
                for (int q = 0; q < nkx; q++) {
                    int base4 = (iys[p]*33 + ixs[q]) * 8;
                    int kk = kys[p]*3 + kxs[q];
                    #pragma unroll
                    for (int c4 = 0; c4 < 8; c4++) {
                        float4 v = __ldg(gin + base4 + c4);
                        float4 w0 = s_w4[kk*16 + c4];
                        float4 w1 = s_w4[kk*16 + 8 + c4];
                        acc0 += v.x*w0.x + v.y*w0.y + v.z*w0.z + v.w*w0.w;
                        acc1 += v.x*w1.x + v.y*w1.y + v.z*w1.z + v.w*w1.w;
                    }
                }
            sT[pix] = acc0;
            sT[NP + pix] = acc1;
        }
    }
    __syncthreads();
    for (int el = tid; el < 2016; el += T) {
        int kk1 = el >> 5, kk2 = el & 31;
        int p = kk1*63 + kk2;
        swcr[kk1*36 + kk2] = sT[2*p];
        swci[kk1*36 + kk2] = sT[2*p + 1];
    }
    __syncthreads();
    for (int el = tid; el < 14904; el += T) sT[el] = 0.f;
    for (int el = tid; el < 4968; el += T) srp[el] = 0.f;
    __syncthreads();

    for (int iter = 0; iter < 5; iter++) {
        // ---- (a) residual -> srp (vectorized 4-wide) ----
        #pragma unroll
        for (int p = 0; p < 2; p++) {
            int w = tid + p*T;
            if (w >= 1008) break;
            int i = w >> 4, g = w & 15, j0 = g << 2;
            const float* x0 = sxp + i*68 + j0;
            float4 r0a = *(const float4*)x0,        r0b = *(const float4*)(x0+4);
            float4 r1a = *(const float4*)(x0+68),   r1b = *(const float4*)(x0+72);
            float4 r2a = *(const float4*)(x0+136),  r2b = *(const float4*)(x0+140);
            float t0[8] = {r0a.x,r0a.y,r0a.z,r0a.w, r0b.x,r0b.y,r0b.z,r0b.w};
            float t1[8] = {r1a.x,r1a.y,r1a.z,r1a.w, r1b.x,r1b.y,r1b.z,r1b.w};
            float t2[8] = {r2a.x,r2a.y,r2a.z,r2a.w, r2b.x,r2b.y,r2b.z,r2b.w};
            float4 A;
            A.x = fr4[p].x - (k0*t0[0]+k1*t0[1]+k2v*t0[2] + k3*t1[0]+k4*t1[1]+k5*t1[2] + k6*t2[0]+k7*t2[1]+k8*t2[2]);
            A.y = fr4[p].y - (k0*t0[1]+k1*t0[2]+k2v*t0[3] + k3*t1[1]+k4*t1[2]+k5*t1[3] + k6*t2[1]+k7*t2[2]+k8*t2[3]);
            A.z = fr4[p].z - (k0*t0[2]+k1*t0[3]+k2v*t0[4] + k3*t1[2]+k4*t1[3]+k5*t1[4] + k6*t2[2]+k7*t2[3]+k8*t2[4]);
            A.w = fr4[p].w - (k0*t0[3]+k1*t0[4]+k2v*t0[5] + k3*t1[3]+k4*t1[4]+k5*t1[5] + k6*t2[3]+k7*t2[4]+k8*t2[5]);
            if (g == 15) A.w = 0.f;
            *(float4*)(srp + (i+3)*72 + 4 + j0) = A;
        }
        __syncthreads();

        // ---- (b) stage1: t[c] = conv7(r, w1[c]) — 2-row blocked, 3 channels ----
        {
            int rpair = tid >> 4, g = tid & 15;
            int i0 = rpair << 1;
            bool two = (i0 + 1 < 63);
            int j0 = g << 2;
            float4 a00={0,0,0,0}, a01={0,0,0,0}, a02={0,0,0,0};
            float4 a10={0,0,0,0}, a11={0,0,0,0}, a12={0,0,0,0};
            #pragma unroll
            for (int rr_ = 0; rr_ < 8; rr_++) {
                if (rr_ == 7 && !two) break;
                const float4* rp4 = (const float4*)(srp + (i0+rr_)*72 + j0);
                float4 Ra = rp4[0], Rb = rp4[1], Rc = rp4[2];
                float rr[12] = {Ra.x,Ra.y,Ra.z,Ra.w, Rb.x,Rb.y,Rb.z,Rb.w, Rc.x,Rc.y,Rc.z,Rc.w};
                if (rr_ < 7) {
                    #pragma unroll
                    for (int v = 0; v < 7; v++) {
                        float w0 = sw1[rr_*7 + v];
                        float w1 = sw1[49 + rr_*7 + v];
                        float w2 = sw1[98 + rr_*7 + v];
                        a00.x += rr[v+1]*w0; a00.y += rr[v+2]*w0; a00.z += rr[v+3]*w0; a00.w += rr[v+4]*w0;
                        a01.x += rr[v+1]*w1; a01.y += rr[v+2]*w1; a01.z += rr[v+3]*w1; a01.w += rr[v+4]*w1;
                        a02.x += rr[v+1]*w2; a02.y += rr[v+2]*w2; a02.z += rr[v+3]*w2; a02.w += rr[v+4]*w2;
                    }
                }
                if (rr_ >= 1) {
                    int u = rr_ - 1;
                    #pragma unroll
                    for (int v = 0; v < 7; v++) {
                        float w0 = sw1[u*7 + v];
                        float w1 = sw1[49 + u*7 + v];
                        float w2 = sw1[98 + u*7 + v];
                        a10.x += rr[v+1]*w0; a10.y += rr[v+2]*w0; a10.z += rr[v+3]*w0; a10.w += rr[v+4]*w0;
                        a11.x += rr[v+1]*w1; a11.y += rr[v+2]*w1; a11.z += rr[v+3]*w1; a11.w += rr[v+4]*w1;
                        a12.x += rr[v+1]*w2; a12.y += rr[v+2]*w2; a12.z += rr[v+3]*w2; a12.w += rr[v+4]*w2;
                    }
                }
            }
            float* o0 = sT + (i0+3)*72 + j0 + 4;
            if (g < 15) {
                *(float4*)o0 = a00; *(float4*)(o0+4968) = a01; *(float4*)(o0+9936) = a02;
                if (two) {
                    float* o1 = o0 + 72;
                    *(float4*)o1 = a10; *(float4*)(o1+4968) = a11; *(float4*)(o1+9936) = a12;
                }
            } else {
                o0[0]=a00.x; o0[1]=a00.y; o0[2]=a00.z;
                o0[4968]=a01.x; o0[4969]=a01.y; o0[4970]=a01.z;
                o0[9936]=a02.x; o0[9937]=a02.y; o0[9938]=a02.z;
                if (two) {
                    float* o1 = o0 + 72;
                    o1[0]=a10.x; o1[1]=a10.y; o1[2]=a10.z;
                    o1[4968]=a11.x; o1[4969]=a11.y; o1[4970]=a11.z;
                    o1[9936]=a12.x; o1[9937]=a12.y; o1[9938]=a12.z;
                }
            }
        }
        __syncthreads();

        // ---- (c) stage2: x += sum_c conv7(t[c], w2[c]) — 4-row x 4-wide ----
        if (tid < 256) {
            int rp = tid >> 4, g = tid & 15;
            int i0 = rp << 2;
            int j0 = g << 2;
            float4 A[4];
            #pragma unroll
            for (int o = 0; o < 4; o++) A[o] = make_float4(0.f,0.f,0.f,0.f);
            #pragma unroll
            for (int c = 0; c < 3; c++) {
                const float* tb = sT + c*4968;
                const float* wc_ = sw2 + c*49;
                #pragma unroll
                for (int rr_ = 0; rr_ < 10; rr_++) {
                    if (i0 + rr_ > 68) break;
                    const float4* rp4 = (const float4*)(tb + (i0+rr_)*72 + j0);
                    float4 Ra = rp4[0], Rb = rp4[1], Rc = rp4[2];
                    float rr[12] = {Ra.x,Ra.y,Ra.z,Ra.w, Rb.x,Rb.y,Rb.z,Rb.w, Rc.x,Rc.y,Rc.z,Rc.w};
                    #pragma unroll
                    for (int o = 0; o < 4; o++) {
                        int u = rr_ - o;
                        if (u < 0 || u > 6) continue;
                        #pragma unroll
                        for (int v = 0; v < 7; v++) {
                            float wv = wc_[u*7 + v];
                            A[o].x += rr[v+1]*wv; A[o].y += rr[v+2]*wv;
                            A[o].z += rr[v+3]*wv; A[o].w += rr[v+4]*wv;
                        }
                    }
                }
            }
            #pragma unroll
            for (int o = 0; o < 4; o++) {
                int i = i0 + o;
                if (i >= 63) break;
                float* xo = sxp + (i+1)*68 + j0 + 1;
                xo[0] += A[o].x; xo[1] += A[o].y; xo[2] += A[o].z;
                if (g < 15) xo[3] += A[o].w;
            }
        }
        __syncthreads();

        // ---- (d) residual -> srp (vectorized) ----
        #pragma unroll
        for (int p = 0; p < 2; p++) {
            int w = tid + p*T;
            if (w >= 1008) break;
            int i = w >> 4, g = w & 15, j0 = g << 2;
            const float* x0 = sxp + i*68 + j0;
            float4 r0a = *(const float4*)x0,        r0b = *(const float4*)(x0+4);
            float4 r1a = *(const float4*)(x0+68),   r1b = *(const float4*)(x0+72);
            float4 r2a = *(const float4*)(x0+136),  r2b = *(const float4*)(x0+140);
            float t0[8] = {r0a.x,r0a.y,r0a.z,r0a.w, r0b.x,r0b.y,r0b.z,r0b.w};
            float t1[8] = {r1a.x,r1a.y,r1a.z,r1a.w, r1b.x,r1b.y,r1b.z,r1b.w};
            float t2[8] = {r2a.x,r2a.y,r2a.z,r2a.w, r2b.x,r2b.y,r2b.z,r2b.w};
            float4 A;
            A.x = fr4[p].x - (k0*t0[0]+k1*t0[1]+k2v*t0[2] + k3*t1[0]+k4*t1[1]+k5*t1[2] + k6*t2[0]+k7*t2[1]+k8*t2[2]);
            A.y = fr4[p].y - (k0*t0[1]+k1*t0[2]+k2v*t0[3] + k3*t1[1]+k4*t1[2]+k5*t1[3] + k6*t2[1]+k7*t2[2]+k8*t2[3]);
            A.z = fr4[p].z - (k0*t0[2]+k1*t0[3]+k2v*t0[4] + k3*t1[2]+k4*t1[3]+k5*t1[4] + k6*t2[2]+k7*t2[3]+k8*t2[4]);
            A.w = fr4[p].w - (k0*t0[3]+k1*t0[4]+k2v*t0[5] + k3*t1[3]+k4*t1[4]+k5*t1[5] + k6*t2[3]+k7*t2[4]+k8*t2[5]);
            if (g == 15) A.w = 0.f;
            *(float4*)(srp + (i+3)*72 + 4 + j0) = A;
        }
        __syncthreads();

        // ---- (P) P[m][k2] = inv * sum_n r[m,n] conj(W[k2,n]) — 2m x 4k2 ----
        if (tid < 256) {
            int mp = tid >> 3, q = tid & 7;
            int m0 = mp << 1, m1 = m0 + 1;
            int k20 = q << 2;
            const float* r0p = srp + (m0+3)*72 + 4;
            const float* r1p = r0p + 72;
            float4 ar0={0,0,0,0}, ai0={0,0,0,0}, ar1={0,0,0,0}, ai1={0,0,0,0};
            #pragma unroll 7
            for (int n = 0; n < 63; n++) {
                float rv0 = r0p[n], rv1 = r1p[n];
                float4 c = *(const float4*)(sttc + n*36 + k20);
                float4 s = *(const float4*)(stts + n*36 + k20);
                ar0.x += rv0*c.x; ar0.y += rv0*c.y; ar0.z += rv0*c.z; ar0.w += rv0*c.w;
                ai0.x -= rv0*s.x; ai0.y -= rv0*s.y; ai0.z -= rv0*s.z; ai0.w -= rv0*s.w;
                ar1.x += rv1*c.x; ar1.y += rv1*c.y; ar1.z += rv1*c.z; ar1.w += rv1*c.w;
                ai1.x -= rv1*s.x; ai1.y -= rv1*s.y; ai1.z -= rv1*s.z; ai1.w -= rv1*s.w;
            }
            float4 R0 = {ar0.x*inv, ar0.y*inv, ar0.z*inv, ar0.w*inv};
            float4 I0 = {ai0.x*inv, ai0.y*inv, ai0.z*inv, ai0.w*inv};
            *(float4*)(sPr + m0*36 + k20) = R0;
            *(float4*)(sPi + m0*36 + k20) = I0;
            if (m1 < 63) {
                float4 R1 = {ar1.x*inv, ar1.y*inv, ar1.z*inv, ar1.w*inv};
                float4 I1 = {ai1.x*inv, ai1.y*inv, ai1.z*inv, ai1.w*inv};
                *(float4*)(sPr + m1*36 + k20) = R1;
                *(float4*)(sPi + m1*36 + k20) = I1;
            }
        }
        __syncthreads();

        // ---- (C) C[k1][k2] = (inv * sum_m conj(W[k1,m]) P[m][k2]) * wc — 2k1 x 4k2 ----
        if (tid < 256) {
            int kp = tid >> 3, q = tid & 7;
            int k10 = kp << 1, k11 = k10 + 1;
            int k11c = (k11 < 63) ? k11 : 62;
            int k20 = q << 2;
            const float2* cs0p = (const float2*)scs + k10*68;
            const float2* cs1p = (const float2*)scs + k11c*68;
            float4 ar0={0,0,0,0}, ai0={0,0,0,0}, ar1={0,0,0,0}, ai1={0,0,0,0};
            #pragma unroll 7
            for (int m = 0; m < 63; m++) {
                float2 cs0 = cs0p[m];
                float2 cs1 = cs1p[m];
                float4 pr = *(const float4*)(sPr + m*36 + k20);
                float4 pi = *(const float4*)(sPi + m*36 + k20);
                ar0.x += cs0.x*pr.x + cs0.y*pi.x;  ai0.x += cs0.x*pi.x - cs0.y*pr.x;
                ar0.y += cs0.x*pr.y + cs0.y*pi.y;  ai0.y += cs0.x*pi.y - cs0.y*pr.y;
                ar0.z += cs0.x*pr.z + cs0.y*pi.z;  ai0.z += cs0.x*pi.z - cs0.y*pr.z;
                ar0.w += cs0.x*pr.w + cs0.y*pi.w;  ai0.w += cs0.x*pi.w - cs0.y*pr.w;
                ar1.x += cs1.x*pr.x + cs1.y*pi.x;  ai1.x += cs1.x*pi.x - cs1.y*pr.x;
                ar1.y += cs1.x*pr.y + cs1.y*pi.y;  ai1.y += cs1.x*pi.y - cs1.y*pr.y;
                ar1.z += cs1.x*pr.z + cs1.y*pi.z;  ai1.z += cs1.x*pi.z - cs1.y*pr.z;
                ar1.w += cs1.x*pr.w + cs1.y*pi.w;  ai1.w += cs1.x*pi.w - cs1.y*pr.w;
            }
            {
                float4 wr = *(const float4*)(swcr + k10*36 + k20);
                float4 wi = *(const float4*)(swci + k10*36 + k20);
                float4 arv = {ar0.x*inv, ar0.y*inv, ar0.z*inv, ar0.w*inv};
                float4 aiv = {ai0.x*inv, ai0.y*inv, ai0.z*inv, ai0.w*inv};
                float4 cr = {arv.x*wr.x - aiv.x*wi.x, arv.y*wr.y - aiv.y*wi.y,
                             arv.z*wr.z - aiv.z*wi.z, arv.w*wr.w - aiv.w*wi.w};
                float4 ci = {arv.x*wi.x + aiv.x*wr.x, arv.y*wi.y + aiv.y*wr.y,
                             arv.z*wi.z + aiv.z*wr.z, arv.w*wi.w + aiv.w*wr.w};
                *(float4*)(sCr + k10*36 + k20) = cr;
                *(float4*)(sCi + k10*36 + k20) = ci;
            }
            if (k11 < 63) {
                float4 wr = *(const float4*)(swcr + k11*36 + k20);
                float4 wi = *(const float4*)(swci + k11*36 + k20);
                float4 arv = {ar1.x*inv, ar1.y*inv, ar1.z*inv, ar1.w*inv};
                float4 aiv = {ai1.x*inv, ai1.y*inv, ai1.z*inv, ai1.w*inv};
                float4 cr = {arv.x*wr.x - aiv.x*wi.x, arv.y*wr.y - aiv.y*wi.y,
                             arv.z*wr.z - aiv.z*wi.z, arv.w*wr.w - aiv.w*wi.w};
                float4 ci = {arv.x*wi.x + aiv.x*wr.x, arv.y*wi.y + aiv.y*wr.y,
                             arv.z*wi.z + aiv.z*wr.z, arv.w*wi.w + aiv.w*wr.w};
                *(float4*)(sCr + k11*36 + k20) = cr;
                *(float4*)(sCi + k11*36 + k20) = ci;
            }
        }
        __syncthreads();

        // ---- (D) D[m][k2] = inv * sum_k1 W[m,k1] C[k1][k2] — 2m x 4k2 ----
        if (tid < 256) {
            int mp = tid >> 3, q = tid & 7;
            int m0 = mp << 1, m1 = m0 + 1;
            int m1c = (m1 < 63) ? m1 : 62;
            int k20 = q << 2;
            const float2* cs0p = (const float2*)scs + m0*68;
            const float2* cs1p = (const float2*)scs + m1c*68;
            float4 dr0={0,0,0,0}, di0={0,0,0,0}, dr1={0,0,0,0}, di1={0,0,0,0};
            #pragma unroll 7
            for (int kk = 0; kk < 63; kk++) {
                float2 cs0 = cs0p[kk];
                float2 cs1 = cs1p[kk];
                float4 Cr = *(const float4*)(sCr + kk*36 + k20);
                float4 Ci = *(const float4*)(sCi + kk*36 + k20);
                dr0.x += cs0.x*Cr.x - cs0.y*Ci.x;  di0.x += cs0.x*Ci.x + cs0.y*Cr.x;
                dr0.y += cs0.x*Cr.y - cs0.y*Ci.y;  di0.y += cs0.x*Ci.y + cs0.y*Cr.y;
                dr0.z += cs0.x*Cr.z - cs0.y*Ci.z;  di0.z += cs0.x*Ci.z + cs0.y*Cr.z;
                dr0.w += cs0.x*Cr.w - cs0.y*Ci.w;  di0.w += cs0.x*Ci.w + cs0.y*Cr.w;
                dr1.x += cs1.x*Cr.x - cs1.y*Ci.x;  di1.x += cs1.x*Ci.x + cs1.y*Cr.x;
                dr1.y += cs1.x*Cr.y - cs1.y*Ci.y;  di1.y += cs1.x*Ci.y + cs1.y*Cr.y;
                dr1.z += cs1.x*Cr.z - cs1.y*Ci.z;  di1.z += cs1.x*Ci.z + cs1.y*Cr.z;
                dr1.w += cs1.x*Cr.w - cs1.y*Ci.w;  di1.w += cs1.x*Ci.w + cs1.y*Cr.w;
            }
            float4 R0 = {dr0.x*inv, dr0.y*inv, dr0.z*inv, dr0.w*inv};
            float4 I0 = {di0.x*inv, di0.y*inv, di0.z*inv, di0.w*inv};
            *(float4*)(sDr + m0*36 + k20) = R0;
            *(float4*)(sDi + m0*36 + k20) = I0;
            if (m1 < 63) {
                float4 R1 = {dr1.x*inv, dr1.y*inv, dr1.z*inv, dr1.w*inv};
                float4 I1 = {di1.x*inv, di1.y*inv, di1.z*inv, di1.w*inv};
                *(float4*)(sDr + m1*36 + k20) = R1;
                *(float4*)(sDi + m1*36 + k20) = I1;
            }
        }
        __syncthreads();

        // ---- (h) x[m,n] += inv*(Dr[m,0] + 2*sum Re(D[m,k2] W[k2,n])) — 2m x 4n ----
        {
            int mp = tid >> 4, g = tid & 15;
            int m0 = mp << 1, m1 = m0 + 1;
            bool two = (m1 < 63);
            int n0 = g << 2;
            const float* d0r = sDr + m0*36;
            const float* d0i = sDi + m0*36;
            const float* d1r = sDr + m1*36;   // m1==63 reads sDi region: harmless, discarded
            const float* d1i = sDi + m1*36;
            float4 A0 = {0,0,0,0}, A1 = {0,0,0,0};
            float b0v = d0r[0], b1v = d1r[0];
            #pragma unroll 8
            for (int kk = 1; kk < 32; kk++) {
                const float* tw = scs + 2*(kk*68 + n0);
                float4 t0 = *(const float4*)tw;       // c(n0) s(n0) c(n0+1) s(n0+1)
                float4 t1 = *(const float4*)(tw + 4); // n0+2, n0+3
                float e0r = d0r[kk]*2.f, e0i = d0i[kk]*2.f;
                float e1r = d1r[kk]*2.f, e1i = d1i[kk]*2.f;
                A0.x += e0r*t0.x - e0i*t0.y;
                A0.y += e0r*t0.z - e0i*t0.w;
                A0.z += e0r*t1.x - e0i*t1.y;
                A0.w += e0r*t1.z - e0i*t1.w;
                A1.x += e1r*t0.x - e1i*t0.y;
                A1.y += e1r*t0.z - e1i*t0.w;
                A1.z += e1r*t1.x - e1i*t1.y;
                A1.w += e1r*t1.z - e1i*t1.w;
            }
            float* xo0 = sxp + (m0+1)*68 + n0 + 1;
            xo0[0] += (b0v + A0.x)*inv;
            xo0[1] += (b0v + A0.y)*inv;
            xo0[2] += (b0v + A0.z)*inv;
            if (g < 15) xo0[3] += (b0v + A0.w)*inv;
            if (two) {
                float* xo1 = sxp + (m1+1)*68 + n0 + 1;
                xo1[0] += (b1v + A1.x)*inv;
                xo1[1] += (b1v + A1.y)*inv;
                xo1[2] += (b1v + A1.z)*inv;
                if (g < 15) xo1[3] += (b1v + A1.w)*inv;
            }
        }
        __syncthreads();
    }

    // ---- final residual + sum of squares (vectorized) ----
    float loc = 0.f;
    #pragma unroll
    for (int p = 0; p < 2; p++) {
        int w = tid + p*T;
        if (w >= 1008) break;
        int i = w >> 4, g = w & 15, j0 = g << 2;
        const float* x0 = sxp + i*68 + j0;
        float4 r0a = *(const float4*)x0,        r0b = *(const float4*)(x0+4);
        float4 r1a = *(const float4*)(x0+68),   r1b = *(const float4*)(x0+72);
        float4 r2a = *(const float4*)(x0+136),  r2b = *(const float4*)(x0+140);
        float t0[8] = {r0a.x,r0a.y,r0a.z,r0a.w, r0b.x,r0b.y,r0b.z,r0b.w};
        float t1[8] = {r1a.x,r1a.y,r1a.z,r1a.w, r1b.x,r1b.y,r1b.z,r1b.w};
        float t2[8] = {r2a.x,r2a.y,r2a.z,r2a.w, r2b.x,r2b.y,r2b.z,r2b.w};
        float4 A;
        A.x = fr4[p].x - (k0*t0[0]+k1*t0[1]+k2v*t0[2] + k3*t1[0]+k4*t1[1]+k5*t1[2] + k6*t2[0]+k7*t2[1]+k8*t2[2]);
        A.y = fr4[p].y - (k0*t0[1]+k1*t0[2]+k2v*t0[3] + k3*t1[1]+k4*t1[2]+k5*t1[3] + k6*t2[1]+k7*t2[2]+k8*t2[3]);
        A.z = fr4[p].z - (k0*t0[2]+k1*t0[3]+k2v*t0[4] + k3*t1[2]+k4*t1[3]+k5*t1[4] + k6*t2[2]+k7*t2[3]+k8*t2[4]);
        A.w = fr4[p].w - (k0*t0[3]+k1*t0[4]+k2v*t0[5] + k3*t1[3]+k4*t1[4]+k5*t1[5] + k6*t2[3]+k7*t2[4]+k8*t2[5]);
        if (g == 15) A.w = 0.f;
        loc += A.x*A.x + A.y*A.y + A.z*A.z + A.w*A.w;
    }
    #pragma unroll
    for (int off = 16; off; off >>= 1)
        loc += __shfl_xor_sync(0xFFFFFFFFu, loc, off);
    __shared__ float wsum[16];
    int wid = tid >> 5;
    if ((tid & 31) == 0) wsum[wid] = loc;
    __syncthreads();
    if (tid == 0) {
        float s = 0.f;
        #pragma unroll
        for (int w = 0; w < 16; w++) s += wsum[w];
        g_blocksum[b] = s;
    }
}

__global__ void final_reduce_kernel(float* __restrict__ out) {
    __shared__ float s[BATCH];
    s[threadIdx.x] = g_blocksum[threadIdx.x];
    __syncthreads();
    for (int st = BATCH/2; st > 0; st >>= 1) {
        if (threadIdx.x < st) s[threadIdx.x] += s[threadIdx.x + st];
        __syncthreads();
    }
    if (threadIdx.x == 0) out[0] = sqrtf(s[0]) / 256.0f;
}

// ---------------- host ----------------
extern "C" void kernel_launch(void* const* d_in, const int* in_sizes, int n_in,
                              void* d_out, int out_size) {
    const float* x      = (const float*)d_in[0];
    const float* f      = (const float*)d_in[1];
    const float* kA     = (const float*)d_in[2];
    const float* fc1_w1 = (const float*)d_in[3];
    const float* fc1_b1 = (const float*)d_in[4];
    const float* fc1_w2 = (const float*)d_in[5];
    const float* fc1_b2 = (const float*)d_in[6];
    const float* fc2_w1 = (const float*)d_in[7];
    const float* fc2_b1 = (const float*)d_in[8];
    const float* fc2_w2 = (const float*)d_in[9];
    const float* fc2_b2 = (const float*)d_in[10];
    const float* ct1_w  = (const float*)d_in[11];
    const float* ct1_b  = (const float*)d_in[12];
    const float* ct2_w  = (const float*)d_in[13];
    const float* ct2_b  = (const float*)d_in[14];
    const float* ct3_w  = (const float*)d_in[15];
    const float* ct3_b  = (const float*)d_in[16];
    const float* ct4_w  = (const float*)d_in[17];
    const float* ct4_b  = (const float*)d_in[18];
    const float* ct5_w  = (const float*)d_in[19];
    const float* ct5_b  = (const float*)d_in[20];
    float* out = (float*)d_out;

    cudaFuncSetAttribute(solver_kernel, cudaFuncAttributeMaxDynamicSharedMemorySize,
                         SMEM_FLOATS * (int)sizeof(float));
    cudaFuncSetAttribute(ctchain_kernel, cudaFuncAttributeMaxDynamicSharedMemorySize,
                         21248 * (int)sizeof(float));

    hyper_kernel<<<BATCH, 256>>>(kA, fc1_w1, fc1_b1, fc1_w2, fc1_b2,
                                 fc2_w1, fc2_b1, fc2_w2, fc2_b2);
    ctchain_kernel<<<BATCH, 512, 21248 * sizeof(float)>>>(kA, ct1_w, ct1_b, ct2_w, ct2_b,
                                                          ct3_w, ct3_b, ct4_w, ct4_b);
    init_tw_kernel<<<(63*68 + 255)/256, 256>>>();
    solver_kernel<<<BATCH, 512, SMEM_FLOATS * sizeof(float)>>>(x, f, kA, ct5_w, ct5_b);
    final_reduce_kernel<<<1, BATCH>>>(out);
}